// round 12
// baseline (speedup 1.0000x reference)
#include <cuda_runtime.h>
#include <cuda_fp16.h>
#include <cstdint>

// ---------------- problem constants ----------------
#define CDIM    256
#define TWIN    49
#define NWIN    2048

// fp16 W (Q|K|V rows 0..767)
__device__ __half g_wh[768 * CDIM];

// ======================= helpers =======================
__device__ __forceinline__ uint32_t smem_u32(const void* p) {
    uint32_t a;
    asm("{ .reg .u64 t; cvta.to.shared.u64 t, %1; cvt.u32.u64 %0, t; }" : "=r"(a) : "l"(p));
    return a;
}
__device__ __forceinline__ void mma_f16(float c[4], const unsigned a[4], const unsigned b[2]) {
    asm volatile(
        "mma.sync.aligned.m16n8k16.row.col.f32.f16.f16.f32 "
        "{%0,%1,%2,%3}, {%4,%5,%6,%7}, {%8,%9}, {%0,%1,%2,%3};"
        : "+f"(c[0]), "+f"(c[1]), "+f"(c[2]), "+f"(c[3])
        : "r"(a[0]), "r"(a[1]), "r"(a[2]), "r"(a[3]), "r"(b[0]), "r"(b[1]));
}
__device__ __forceinline__ unsigned pack_h2(float lo, float hi) {
    __half2 h = __float22half2_rn(make_float2(lo, hi));
    return *(unsigned*)&h;
}

#define CP_ASYNC16(dst, src) \
    asm volatile("cp.async.cg.shared.global [%0], [%1], 16;" :: "r"(dst), "l"(src))
#define CP_COMMIT() asm volatile("cp.async.commit_group;" ::: "memory")
#define CP_WAIT1()  asm volatile("cp.async.wait_group 1;" ::: "memory")
#define CP_WAIT0()  asm volatile("cp.async.wait_group 0;" ::: "memory")

// ================= Kernel 0: W -> fp16 =================
__global__ void __launch_bounds__(256) pre_w(
    const float* __restrict__ Wq, const float* __restrict__ Wk, const float* __restrict__ Wv)
{
    const int r    = blockIdx.x * 8 + (threadIdx.x >> 5);   // 0..767
    const int lane = threadIdx.x & 31;
    const int pr   = r >> 8, wr = r & 255;
    const float* W = (pr == 0) ? Wq : ((pr == 1) ? Wk : Wv);
    const float* src = W + (size_t)wr * CDIM + lane * 8;
    __half* dst = g_wh + (size_t)r * CDIM + lane * 8;
    float4 v0 = *(const float4*)(src);
    float4 v1 = *(const float4*)(src + 4);
    __half2 o[4];
    o[0] = __float22half2_rn(make_float2(v0.x, v0.y));
    o[1] = __float22half2_rn(make_float2(v0.z, v0.w));
    o[2] = __float22half2_rn(make_float2(v1.x, v1.y));
    o[3] = __float22half2_rn(make_float2(v1.z, v1.w));
    *(uint4*)dst = *(uint4*)o;
}

// ================= Fused kernel: gather + QKV proj + attention =================
// smem layout (halves):
//   A_s  [64][264]   @ 0        (gathered x, fp16; rows 49..63 zero)
//   Q_s  [64][264]   @ 16896
//   K_s  [64][264]   @ 33792
//   VT_s [256][72]   @ 50688    (V transposed: row = d, col = token j)
//   B_s  [3][128][72]@ 69120    (W chunk, 3-stage; 64 k-halves + 8 pad per row)
//   bias [768 f32]   @ 96768 halves
#define SM_A   0
#define SM_Q   16896
#define SM_K   33792
#define SM_VT  50688
#define SM_B   69120
#define SM_BIAS 96768
#define FUSED_SMEM_BYTES ((96768 + 1536) * 2)   // 196608 B

__global__ void __launch_bounds__(256) fused_swin(
    const float* __restrict__ x,
    const float* __restrict__ bq, const float* __restrict__ bk, const float* __restrict__ bv,
    float* __restrict__ out)
{
    extern __shared__ __align__(16) __half sm[];
    __half* A_s  = sm + SM_A;
    __half* Q_s  = sm + SM_Q;
    __half* K_s  = sm + SM_K;
    __half* VT_s = sm + SM_VT;
    float*  bias_s = (float*)(sm + SM_BIAS);

    const int tid  = threadIdx.x;
    const int warp = tid >> 5;
    const int lane = tid & 31;
    const int g    = lane >> 2;
    const int tig  = lane & 3;
    const int w    = blockIdx.x;

    const uint32_t sbase = smem_u32(sm);

    // ---- B chunk loader: chunk c (0..23): W rows (c>>2)*128.., k halves (c&3)*64.. ----
    auto issue_B = [&](int c) {
        const int buf   = c % 3;
        const int nrow0 = (c >> 2) * 128;
        const int kofs  = (c & 3) * 64;
        #pragma unroll
        for (int i = 0; i < 4; i++) {
            int s  = tid + i * 256;          // 0..1023
            int r  = s >> 3;
            int sg = s & 7;
            uint32_t dst = sbase + (uint32_t)(SM_B + buf * 9216 + r * 72 + sg * 8) * 2;
            CP_ASYNC16(dst, g_wh + (size_t)(nrow0 + r) * CDIM + kofs + sg * 8);
        }
        CP_COMMIT();
    };

    issue_B(0);
    issue_B(1);

    // ---- bias preload ----
    for (int i = tid; i < 768; i += 256)
        bias_s[i] = (i < 256) ? bq[i] : ((i < 512) ? bk[i - 256] : bv[i - 512]);

    // ---- gather window rows of x -> A_s (fp16), zero pad rows ----
    {
        const int b = w >> 6, wi = w & 63, wy = wi >> 3, wx = wi & 7;
        for (int idx = tid; idx < TWIN * 32; idx += 256) {
            int t = idx >> 5, s = idx & 31;
            int ty = t / 7, tx = t - ty * 7;
            const float* src = x + (size_t)((b * 56 + wy * 7 + ty) * 56 + wx * 7 + tx) * CDIM + s * 8;
            float4 v0 = *(const float4*)(src);
            float4 v1 = *(const float4*)(src + 4);
            __half2 o[4];
            o[0] = __float22half2_rn(make_float2(v0.x, v0.y));
            o[1] = __float22half2_rn(make_float2(v0.z, v0.w));
            o[2] = __float22half2_rn(make_float2(v1.x, v1.y));
            o[3] = __float22half2_rn(make_float2(v1.z, v1.w));
            *(uint4*)(A_s + t * 264 + s * 8) = *(uint4*)o;
        }
        for (int idx = tid; idx < 15 * 33; idx += 256) {
            int t = 49 + idx / 33, s = idx - (idx / 33) * 33;
            *(uint4*)(A_s + t * 264 + s * 8) = make_uint4(0, 0, 0, 0);
        }
    }
    __syncthreads();

    // ================= GEMM: QKV = A @ W^T + b =================
    const uint32_t* Aw = (const uint32_t*)A_s;   // word stride 132
    const int wm  = warp & 1;     // 32-row half
    const int wnn = warp >> 2 == 0 ? (warp >> 1) : (warp >> 1);  // placeholder (fixed below)
    const int wn4 = warp >> 1;    // 0..3: 32-col group within 128-chunk

    float acc[2][4][4];

    for (int c = 0; c < 24; c++) {
        if ((c & 3) == 0) {
            #pragma unroll
            for (int mt = 0; mt < 2; mt++)
                #pragma unroll
                for (int nt = 0; nt < 4; nt++)
                    #pragma unroll
                    for (int q = 0; q < 4; q++) acc[mt][nt][q] = 0.f;
        }

        if (c < 23) { CP_WAIT1(); } else { CP_WAIT0(); }
        __syncthreads();
        if (c + 2 < 24) issue_B(c + 2);

        const uint32_t* Bw = (const uint32_t*)(sm + SM_B + (c % 3) * 9216);   // word stride 36

        #pragma unroll
        for (int ks = 0; ks < 4; ks++) {
            const int ka = (c & 3) * 32 + ks * 8;   // A word k-offset
            unsigned a[2][4], bb[4][2];
            #pragma unroll
            for (int mt = 0; mt < 2; mt++) {
                int row = wm * 32 + mt * 16 + g;
                a[mt][0] = Aw[row * 132 + ka + tig];
                a[mt][1] = Aw[(row + 8) * 132 + ka + tig];
                a[mt][2] = Aw[row * 132 + ka + 4 + tig];
                a[mt][3] = Aw[(row + 8) * 132 + ka + 4 + tig];
            }
            #pragma unroll
            for (int nt = 0; nt < 4; nt++) {
                int nr = wn4 * 32 + nt * 8 + g;
                bb[nt][0] = Bw[nr * 36 + ks * 8 + tig];
                bb[nt][1] = Bw[nr * 36 + ks * 8 + 4 + tig];
            }
            #pragma unroll
            for (int mt = 0; mt < 2; mt++)
                #pragma unroll
                for (int nt = 0; nt < 4; nt++)
                    mma_f16(acc[mt][nt], a[mt], bb[nt]);
        }

        // ---- per-n-chunk epilogue: bias + store into Q_s / K_s / VT_s ----
        if ((c & 3) == 3) {
            const int nc   = c >> 2;       // 0..5
            const int proj = nc >> 1;      // 0=Q,1=K,2=V
            #pragma unroll
            for (int mt = 0; mt < 2; mt++) {
                const int r0 = wm * 32 + mt * 16 + g;
                #pragma unroll
                for (int nt = 0; nt < 4; nt++) {
                    const int dfull = nc * 128 + wn4 * 32 + nt * 8 + tig * 2;  // 0..766
                    const int d     = dfull & 255;
                    const float b0 = bias_s[dfull], b1 = bias_s[dfull + 1];
                    const float c00 = acc[mt][nt][0] + b0, c01 = acc[mt][nt][1] + b1;
                    const float c10 = acc[mt][nt][2] + b0, c11 = acc[mt][nt][3] + b1;
                    if (proj == 0) {
                        *(uint32_t*)(Q_s + r0 * 264 + d)       = pack_h2(c00, c01);
                        *(uint32_t*)(Q_s + (r0 + 8) * 264 + d) = pack_h2(c10, c11);
                    } else if (proj == 1) {
                        *(uint32_t*)(K_s + r0 * 264 + d)       = pack_h2(c00, c01);
                        *(uint32_t*)(K_s + (r0 + 8) * 264 + d) = pack_h2(c10, c11);
                    } else {
                        VT_s[d * 72 + r0]           = __float2half_rn(c00);
                        VT_s[(d + 1) * 72 + r0]     = __float2half_rn(c01);
                        VT_s[d * 72 + r0 + 8]       = __float2half_rn(c10);
                        VT_s[(d + 1) * 72 + r0 + 8] = __float2half_rn(c11);
                    }
                }
            }
        }
    }

    __syncthreads();

    // ================= Attention: warp = head =================
    const int h  = warp;            // 0..7
    const int hw = h * 16;          // head word offset in Q_s/K_s rows
    const uint32_t* qw = (const uint32_t*)Q_s;    // word stride 132
    const uint32_t* kw = (const uint32_t*)K_s;
    const uint32_t* vw = (const uint32_t*)VT_s;   // word stride 36

    for (int qt = 0; qt < 4; qt++) {
        const int i0 = qt * 16;

        // ---- QK^T ----
        float at[7][4] = {};
        #pragma unroll
        for (int ks16 = 0; ks16 < 2; ks16++) {
            const int c0 = hw + ks16 * 8;
            unsigned a[4];
            a[0] = qw[(i0 + g) * 132 + c0 + tig];
            a[1] = qw[(i0 + g + 8) * 132 + c0 + tig];
            a[2] = qw[(i0 + g) * 132 + c0 + 4 + tig];
            a[3] = qw[(i0 + g + 8) * 132 + c0 + 4 + tig];
            #pragma unroll
            for (int nt = 0; nt < 7; nt++) {
                unsigned b[2];
                b[0] = kw[(nt * 8 + g) * 132 + c0 + tig];
                b[1] = kw[(nt * 8 + g) * 132 + c0 + 4 + tig];
                mma_f16(at[nt], a, b);
            }
        }

        // ---- scale + mask padded key cols (j >= 49) ----
        #pragma unroll
        for (int nt = 0; nt < 7; nt++) {
            at[nt][0] *= 0.0625f; at[nt][1] *= 0.0625f;
            at[nt][2] *= 0.0625f; at[nt][3] *= 0.0625f;
        }
        at[6][1] = -1e30f; at[6][3] = -1e30f;
        if (tig > 0) { at[6][0] = -1e30f; at[6][2] = -1e30f; }

        // ---- softmax on fragments ----
        float m0 = -1e30f, m1 = -1e30f;
        #pragma unroll
        for (int nt = 0; nt < 7; nt++) {
            m0 = fmaxf(m0, fmaxf(at[nt][0], at[nt][1]));
            m1 = fmaxf(m1, fmaxf(at[nt][2], at[nt][3]));
        }
        m0 = fmaxf(m0, __shfl_xor_sync(0xffffffffu, m0, 1));
        m0 = fmaxf(m0, __shfl_xor_sync(0xffffffffu, m0, 2));
        m1 = fmaxf(m1, __shfl_xor_sync(0xffffffffu, m1, 1));
        m1 = fmaxf(m1, __shfl_xor_sync(0xffffffffu, m1, 2));

        float s0 = 0.f, s1 = 0.f;
        #pragma unroll
        for (int nt = 0; nt < 7; nt++) {
            at[nt][0] = __expf(at[nt][0] - m0);
            at[nt][1] = __expf(at[nt][1] - m0);
            at[nt][2] = __expf(at[nt][2] - m1);
            at[nt][3] = __expf(at[nt][3] - m1);
            s0 += at[nt][0] + at[nt][1];
            s1 += at[nt][2] + at[nt][3];
        }
        s0 += __shfl_xor_sync(0xffffffffu, s0, 1);
        s0 += __shfl_xor_sync(0xffffffffu, s0, 2);
        s1 += __shfl_xor_sync(0xffffffffu, s1, 1);
        s1 += __shfl_xor_sync(0xffffffffu, s1, 2);
        const float inv0 = 1.f / s0, inv1 = 1.f / s1;
        #pragma unroll
        for (int nt = 0; nt < 7; nt++) {
            at[nt][0] *= inv0; at[nt][1] *= inv0;
            at[nt][2] *= inv1; at[nt][3] *= inv1;
        }

        // ---- PV (C-frag == A-frag via half2 pack) ----
        float oacc[4][4] = {};
        #pragma unroll
        for (int t = 0; t < 4; t++) {
            const int n0 = 2 * t, n1 = 2 * t + 1;
            unsigned pa[4];
            pa[0] = pack_h2(at[n0][0], at[n0][1]);
            pa[1] = pack_h2(at[n0][2], at[n0][3]);
            pa[2] = (n1 < 7) ? pack_h2(at[n1][0], at[n1][1]) : 0u;
            pa[3] = (n1 < 7) ? pack_h2(at[n1][2], at[n1][3]) : 0u;
            #pragma unroll
            for (int dt = 0; dt < 4; dt++) {
                unsigned b[2];
                b[0] = vw[(h * 32 + dt * 8 + g) * 36 + 8 * t + tig];
                b[1] = vw[(h * 32 + dt * 8 + g) * 36 + 8 * t + tig + 4];
                mma_f16(oacc[dt], pa, b);
            }
        }

        // ---- store ----
        const int row0 = i0 + g;
        const int row1 = i0 + 8 + g;
        if (row0 < TWIN) {
            float* o = out + ((size_t)w * TWIN + row0) * CDIM + (size_t)h * 32;
            #pragma unroll
            for (int dt = 0; dt < 4; dt++)
                *(float2*)&o[dt * 8 + tig * 2] = make_float2(oacc[dt][0], oacc[dt][1]);
        }
        if (row1 < TWIN) {
            float* o = out + ((size_t)w * TWIN + row1) * CDIM + (size_t)h * 32;
            #pragma unroll
            for (int dt = 0; dt < 4; dt++)
                *(float2*)&o[dt * 8 + tig * 2] = make_float2(oacc[dt][2], oacc[dt][3]);
        }
    }
}

// ================= launch =================
extern "C" void kernel_launch(void* const* d_in, const int* in_sizes, int n_in,
                              void* d_out, int out_size) {
    const float* x  = (const float*)d_in[0];
    const float* Wq = (const float*)d_in[1];
    const float* bq = (const float*)d_in[2];
    const float* Wk = (const float*)d_in[3];
    const float* bk = (const float*)d_in[4];
    const float* Wv = (const float*)d_in[5];
    const float* bv = (const float*)d_in[6];
    float* out = (float*)d_out;

    cudaFuncSetAttribute(fused_swin,
                         cudaFuncAttributeMaxDynamicSharedMemorySize, FUSED_SMEM_BYTES);

    pre_w<<<96, 256>>>(Wq, Wk, Wv);
    fused_swin<<<NWIN, 256, FUSED_SMEM_BYTES>>>(x, bq, bk, bv, out);
}

// round 13
// speedup vs baseline: 1.0559x; 1.0559x over previous
#include <cuda_runtime.h>
#include <cuda_fp16.h>
#include <cstdint>

// ---------------- problem constants ----------------
#define CDIM    256
#define TWIN    49
#define NWIN    2048

// fp16 W (Q|K|V rows 0..767)
__device__ __half g_wh[768 * CDIM];

// ======================= helpers =======================
__device__ __forceinline__ uint32_t smem_u32(const void* p) {
    uint32_t a;
    asm("{ .reg .u64 t; cvta.to.shared.u64 t, %1; cvt.u32.u64 %0, t; }" : "=r"(a) : "l"(p));
    return a;
}
__device__ __forceinline__ void mma_f16(float c[4], const unsigned a[4], const unsigned b[2]) {
    asm volatile(
        "mma.sync.aligned.m16n8k16.row.col.f32.f16.f16.f32 "
        "{%0,%1,%2,%3}, {%4,%5,%6,%7}, {%8,%9}, {%0,%1,%2,%3};"
        : "+f"(c[0]), "+f"(c[1]), "+f"(c[2]), "+f"(c[3])
        : "r"(a[0]), "r"(a[1]), "r"(a[2]), "r"(a[3]), "r"(b[0]), "r"(b[1]));
}
__device__ __forceinline__ unsigned pack_h2(float lo, float hi) {
    __half2 h = __float22half2_rn(make_float2(lo, hi));
    return *(unsigned*)&h;
}

#define CP_ASYNC16(dst, src) \
    asm volatile("cp.async.cg.shared.global [%0], [%1], 16;" :: "r"(dst), "l"(src))
#define CP_COMMIT() asm volatile("cp.async.commit_group;" ::: "memory")
#define CP_WAIT1()  asm volatile("cp.async.wait_group 1;" ::: "memory")
#define CP_WAIT0()  asm volatile("cp.async.wait_group 0;" ::: "memory")

// ================= Kernel 0: W -> fp16 =================
__global__ void __launch_bounds__(256) pre_w(
    const float* __restrict__ Wq, const float* __restrict__ Wk, const float* __restrict__ Wv)
{
    const int r    = blockIdx.x * 8 + (threadIdx.x >> 5);   // 0..767
    const int lane = threadIdx.x & 31;
    const int pr   = r >> 8, wr = r & 255;
    const float* W = (pr == 0) ? Wq : ((pr == 1) ? Wk : Wv);
    const float* src = W + (size_t)wr * CDIM + lane * 8;
    __half* dst = g_wh + (size_t)r * CDIM + lane * 8;
    float4 v0 = *(const float4*)(src);
    float4 v1 = *(const float4*)(src + 4);
    __half2 o[4];
    o[0] = __float22half2_rn(make_float2(v0.x, v0.y));
    o[1] = __float22half2_rn(make_float2(v0.z, v0.w));
    o[2] = __float22half2_rn(make_float2(v1.x, v1.y));
    o[3] = __float22half2_rn(make_float2(v1.z, v1.w));
    *(uint4*)dst = *(uint4*)o;
}

// ================= Fused kernel: gather + QKV proj + attention =================
// smem (halves):
//   A_s  [49][264] @ 0       (gathered x fp16)
//   Q_s  [49][264] @ 12936
//   K_s  [49][264] @ 25872
//   B_s  [3][64][72] @ 38808 (W chunk stream)
//   VT_s [256][72] @ 12936   (aliases Q+K after attention phase; V transposed)
// total 52632 halves = 105264 B  ->  2 CTAs/SM
#define SM_A   0
#define SM_Q   12936
#define SM_K   25872
#define SM_B   38808
#define SM_VT  12936
#define FUSED_SMEM_BYTES (52632 * 2)

__global__ void __launch_bounds__(256, 2) fused_swin(
    const float* __restrict__ x,
    const float* __restrict__ bq, const float* __restrict__ bk, const float* __restrict__ bv,
    float* __restrict__ out)
{
    extern __shared__ __align__(16) __half sm[];

    const int tid  = threadIdx.x;
    const int warp = tid >> 5;
    const int lane = tid & 31;
    const int g    = lane >> 2;
    const int tig  = lane & 3;
    const int w    = blockIdx.x;

    const uint32_t sbase = smem_u32(sm);

    // ---- B chunk loader: chunk c: W rows (c>>2)*64 .. +63, k halves (c&3)*64 .. +63 ----
    auto issue_B = [&](int c) {
        const int buf   = c % 3;
        const int nrow0 = (c >> 2) * 64;
        const int kofs  = (c & 3) * 64;
        #pragma unroll
        for (int i = 0; i < 2; i++) {
            int s  = tid + i * 256;     // 0..511 (64 rows x 8 segs)
            int r  = s >> 3;
            int sg = s & 7;
            uint32_t dst = sbase + (uint32_t)(SM_B + buf * 4608 + r * 72 + sg * 8) * 2;
            CP_ASYNC16(dst, g_wh + (size_t)(nrow0 + r) * CDIM + kofs + sg * 8);
        }
        CP_COMMIT();
    };

    issue_B(0);
    issue_B(1);

    // ---- gather window rows of x -> A_s (fp16) ----
    {
        const int b = w >> 6, wi = w & 63, wy = wi >> 3, wx = wi & 7;
        for (int idx = tid; idx < TWIN * 32; idx += 256) {
            int t = idx >> 5, s = idx & 31;
            int ty = t / 7, tx = t - ty * 7;
            const float* src = x + (size_t)((b * 56 + wy * 7 + ty) * 56 + wx * 7 + tx) * CDIM + s * 8;
            float4 v0 = *(const float4*)(src);
            float4 v1 = *(const float4*)(src + 4);
            __half2 o[4];
            o[0] = __float22half2_rn(make_float2(v0.x, v0.y));
            o[1] = __float22half2_rn(make_float2(v0.z, v0.w));
            o[2] = __float22half2_rn(make_float2(v1.x, v1.y));
            o[3] = __float22half2_rn(make_float2(v1.z, v1.w));
            *(uint4*)(sm + SM_A + t * 264 + s * 8) = *(uint4*)o;
        }
    }
    __syncthreads();

    const int wm  = warp & 1;            // m half
    const int wn  = warp >> 1;           // 0..3: 16-col group within 64-row n-chunk
    const int m0_0 = wm ? 32 : 0;        // m-tile bases (wm=1 tiles overlap rows 33..47)
    const int m0_1 = wm ? 33 : 16;

    const uint32_t* Aw = (const uint32_t*)(sm + SM_A);   // word stride 132

    float acc[2][2][4];
    unsigned P[4][14];                   // packed softmax(P) per query tile

    for (int c = 0; c < 48; c++) {
        if (c == 32) {
            // ======== attention phase: QK^T + softmax, P -> registers ========
            __syncthreads();             // K epilogue (c=31) visible
            {
                const int h  = warp;
                const int hw = h * 16;
                const uint32_t* qw = (const uint32_t*)(sm + SM_Q);
                const uint32_t* kw = (const uint32_t*)(sm + SM_K);
                #pragma unroll
                for (int qt = 0; qt < 4; qt++) {
                    const int i0 = qt * 16;
                    float at[7][4] = {};
                    #pragma unroll
                    for (int ks16 = 0; ks16 < 2; ks16++) {
                        const int c0 = hw + ks16 * 8;
                        unsigned a[4];
                        a[0] = qw[(i0 + g) * 132 + c0 + tig];
                        a[1] = qw[(i0 + g + 8) * 132 + c0 + tig];
                        a[2] = qw[(i0 + g) * 132 + c0 + 4 + tig];
                        a[3] = qw[(i0 + g + 8) * 132 + c0 + 4 + tig];
                        #pragma unroll
                        for (int nt = 0; nt < 7; nt++) {
                            unsigned b[2];
                            b[0] = kw[(nt * 8 + g) * 132 + c0 + tig];
                            b[1] = kw[(nt * 8 + g) * 132 + c0 + 4 + tig];
                            mma_f16(at[nt], a, b);
                        }
                    }
                    #pragma unroll
                    for (int nt = 0; nt < 7; nt++) {
                        at[nt][0] *= 0.0625f; at[nt][1] *= 0.0625f;
                        at[nt][2] *= 0.0625f; at[nt][3] *= 0.0625f;
                    }
                    at[6][1] = -1e30f; at[6][3] = -1e30f;
                    if (tig > 0) { at[6][0] = -1e30f; at[6][2] = -1e30f; }

                    float m0 = -1e30f, m1 = -1e30f;
                    #pragma unroll
                    for (int nt = 0; nt < 7; nt++) {
                        m0 = fmaxf(m0, fmaxf(at[nt][0], at[nt][1]));
                        m1 = fmaxf(m1, fmaxf(at[nt][2], at[nt][3]));
                    }
                    m0 = fmaxf(m0, __shfl_xor_sync(0xffffffffu, m0, 1));
                    m0 = fmaxf(m0, __shfl_xor_sync(0xffffffffu, m0, 2));
                    m1 = fmaxf(m1, __shfl_xor_sync(0xffffffffu, m1, 1));
                    m1 = fmaxf(m1, __shfl_xor_sync(0xffffffffu, m1, 2));

                    float s0 = 0.f, s1 = 0.f;
                    #pragma unroll
                    for (int nt = 0; nt < 7; nt++) {
                        at[nt][0] = __expf(at[nt][0] - m0);
                        at[nt][1] = __expf(at[nt][1] - m0);
                        at[nt][2] = __expf(at[nt][2] - m1);
                        at[nt][3] = __expf(at[nt][3] - m1);
                        s0 += at[nt][0] + at[nt][1];
                        s1 += at[nt][2] + at[nt][3];
                    }
                    s0 += __shfl_xor_sync(0xffffffffu, s0, 1);
                    s0 += __shfl_xor_sync(0xffffffffu, s0, 2);
                    s1 += __shfl_xor_sync(0xffffffffu, s1, 1);
                    s1 += __shfl_xor_sync(0xffffffffu, s1, 2);
                    const float inv0 = 1.f / s0, inv1 = 1.f / s1;
                    #pragma unroll
                    for (int nt = 0; nt < 7; nt++) {
                        at[nt][0] *= inv0; at[nt][1] *= inv0;
                        at[nt][2] *= inv1; at[nt][3] *= inv1;
                    }
                    #pragma unroll
                    for (int t = 0; t < 3; t++) {
                        P[qt][4 * t + 0] = pack_h2(at[2 * t][0], at[2 * t][1]);
                        P[qt][4 * t + 1] = pack_h2(at[2 * t][2], at[2 * t][3]);
                        P[qt][4 * t + 2] = pack_h2(at[2 * t + 1][0], at[2 * t + 1][1]);
                        P[qt][4 * t + 3] = pack_h2(at[2 * t + 1][2], at[2 * t + 1][3]);
                    }
                    P[qt][12] = pack_h2(at[6][0], at[6][1]);
                    P[qt][13] = pack_h2(at[6][2], at[6][3]);
                }
            }
            __syncthreads();             // all warps done reading Q/K
            // zero VT pad cols 48..71 (col 48 rewritten by V epilogue later)
            {
                __half* VT = sm + SM_VT;
                uint4 z = make_uint4(0, 0, 0, 0);
                *(uint4*)(VT + tid * 72 + 48) = z;
                *(uint4*)(VT + tid * 72 + 56) = z;
                *(uint4*)(VT + tid * 72 + 64) = z;
            }
        }

        if (c < 47) { CP_WAIT1(); } else { CP_WAIT0(); }
        __syncthreads();
        if (c + 2 < 48) issue_B(c + 2);

        const int kc = c & 3;
        if (kc == 0) {
            #pragma unroll
            for (int mt = 0; mt < 2; mt++)
                #pragma unroll
                for (int nt = 0; nt < 2; nt++)
                    #pragma unroll
                    for (int q = 0; q < 4; q++) acc[mt][nt][q] = 0.f;
        }

        const uint32_t* Bw = (const uint32_t*)(sm + SM_B + (c % 3) * 4608);   // word stride 36

        #pragma unroll
        for (int ks = 0; ks < 4; ks++) {
            const int ka = kc * 32 + ks * 8;
            unsigned a0[4], a1[4], bb[2][2];
            a0[0] = Aw[(m0_0 + g) * 132 + ka + tig];
            a0[1] = Aw[(m0_0 + 8 + g) * 132 + ka + tig];
            a0[2] = Aw[(m0_0 + g) * 132 + ka + 4 + tig];
            a0[3] = Aw[(m0_0 + 8 + g) * 132 + ka + 4 + tig];
            a1[0] = Aw[(m0_1 + g) * 132 + ka + tig];
            a1[1] = Aw[(m0_1 + 8 + g) * 132 + ka + tig];
            a1[2] = Aw[(m0_1 + g) * 132 + ka + 4 + tig];
            a1[3] = Aw[(m0_1 + 8 + g) * 132 + ka + 4 + tig];
            #pragma unroll
            for (int nt = 0; nt < 2; nt++) {
                int nr = wn * 16 + nt * 8 + g;
                bb[nt][0] = Bw[nr * 36 + ks * 8 + tig];
                bb[nt][1] = Bw[nr * 36 + ks * 8 + 4 + tig];
            }
            #pragma unroll
            for (int nt = 0; nt < 2; nt++) {
                mma_f16(acc[0][nt], a0, bb[nt]);
                mma_f16(acc[1][nt], a1, bb[nt]);
            }
        }

        // ---- per-n-chunk epilogue ----
        if (kc == 3) {
            const int nc   = c >> 2;     // 0..11
            const int proj = nc >> 2;    // 0=Q,1=K,2=V
            const float* __restrict__ bias = (proj == 0) ? bq : ((proj == 1) ? bk : bv);
            __half* dstQ = sm + ((proj == 0) ? SM_Q : SM_K);
            __half* VT   = sm + SM_VT;
            #pragma unroll
            for (int nt = 0; nt < 2; nt++) {
                const int d  = (nc & 3) * 64 + wn * 16 + nt * 8 + tig * 2;   // 0..254
                const float b0 = __ldg(bias + d);
                const float b1 = __ldg(bias + d + 1);
                #pragma unroll
                for (int mt = 0; mt < 2; mt++) {
                    const int r0 = (mt == 0 ? m0_0 : m0_1) + g;
                    const float c00 = acc[mt][nt][0] + b0, c01 = acc[mt][nt][1] + b1;
                    const float c10 = acc[mt][nt][2] + b0, c11 = acc[mt][nt][3] + b1;
                    if (proj < 2) {
                        *(uint32_t*)(dstQ + r0 * 264 + d)       = pack_h2(c00, c01);
                        *(uint32_t*)(dstQ + (r0 + 8) * 264 + d) = pack_h2(c10, c11);
                    } else {
                        VT[d * 72 + r0]           = __float2half_rn(c00);
                        VT[(d + 1) * 72 + r0]     = __float2half_rn(c01);
                        VT[d * 72 + r0 + 8]       = __float2half_rn(c10);
                        VT[(d + 1) * 72 + r0 + 8] = __float2half_rn(c11);
                    }
                }
            }
        }
    }

    __syncthreads();

    // ======== PV + output ========
    {
        const int h = warp;
        const uint32_t* vw = (const uint32_t*)(sm + SM_VT);   // word stride 36
        #pragma unroll
        for (int qt = 0; qt < 4; qt++) {
            const int i0 = qt * 16;
            float oacc[4][4] = {};
            #pragma unroll
            for (int t = 0; t < 4; t++) {
                unsigned pa[4];
                if (t < 3) {
                    pa[0] = P[qt][4 * t + 0];
                    pa[1] = P[qt][4 * t + 1];
                    pa[2] = P[qt][4 * t + 2];
                    pa[3] = P[qt][4 * t + 3];
                } else {
                    pa[0] = P[qt][12];
                    pa[1] = P[qt][13];
                    pa[2] = 0u;
                    pa[3] = 0u;
                }
                #pragma unroll
                for (int dt = 0; dt < 4; dt++) {
                    unsigned b[2];
                    b[0] = vw[(h * 32 + dt * 8 + g) * 36 + 8 * t + tig];
                    b[1] = vw[(h * 32 + dt * 8 + g) * 36 + 8 * t + tig + 4];
                    mma_f16(oacc[dt], pa, b);
                }
            }
            const int row0 = i0 + g;
            const int row1 = i0 + 8 + g;
            if (row0 < TWIN) {
                float* o = out + ((size_t)w * TWIN + row0) * CDIM + (size_t)h * 32;
                #pragma unroll
                for (int dt = 0; dt < 4; dt++)
                    *(float2*)&o[dt * 8 + tig * 2] = make_float2(oacc[dt][0], oacc[dt][1]);
            }
            if (row1 < TWIN) {
                float* o = out + ((size_t)w * TWIN + row1) * CDIM + (size_t)h * 32;
                #pragma unroll
                for (int dt = 0; dt < 4; dt++)
                    *(float2*)&o[dt * 8 + tig * 2] = make_float2(oacc[dt][2], oacc[dt][3]);
            }
        }
    }
}

// ================= launch =================
extern "C" void kernel_launch(void* const* d_in, const int* in_sizes, int n_in,
                              void* d_out, int out_size) {
    const float* x  = (const float*)d_in[0];
    const float* Wq = (const float*)d_in[1];
    const float* bq = (const float*)d_in[2];
    const float* Wk = (const float*)d_in[3];
    const float* bk = (const float*)d_in[4];
    const float* Wv = (const float*)d_in[5];
    const float* bv = (const float*)d_in[6];
    float* out = (float*)d_out;

    cudaFuncSetAttribute(fused_swin,
                         cudaFuncAttributeMaxDynamicSharedMemorySize, FUSED_SMEM_BYTES);

    pre_w<<<96, 256>>>(Wq, Wk, Wv);
    fused_swin<<<NWIN, 256, FUSED_SMEM_BYTES>>>(x, bq, bk, bv, out);
}

// round 14
// speedup vs baseline: 1.3960x; 1.3221x over previous
#include <cuda_runtime.h>
#include <cuda_fp16.h>
#include <cstdint>

// ---------------- problem constants ----------------
#define M_TOK   100352          // 32 * 64 * 49 tokens (window-gathered order)
#define CDIM    256
#define NHEADS  8
#define HD      32
#define TWIN    49
#define NWIN    2048

// scratch (all fp16 intermediates)
__device__ __half g_qkvh[3ull * M_TOK * CDIM];  // Q|K|V, window-gathered rows
__device__ __half g_xh[(size_t)M_TOK * CDIM];   // gathered x
__device__ __half g_wh[768 * CDIM];             // Wq|Wk|Wv

// ======================= helpers =======================
__device__ __forceinline__ uint32_t smem_u32(const void* p) {
    uint32_t a;
    asm("{ .reg .u64 t; cvta.to.shared.u64 t, %1; cvt.u32.u64 %0, t; }" : "=r"(a) : "l"(p));
    return a;
}
__device__ __forceinline__ void mma_f16(float c[4], const unsigned a[4], const unsigned b[2]) {
    asm volatile(
        "mma.sync.aligned.m16n8k16.row.col.f32.f16.f16.f32 "
        "{%0,%1,%2,%3}, {%4,%5,%6,%7}, {%8,%9}, {%0,%1,%2,%3};"
        : "+f"(c[0]), "+f"(c[1]), "+f"(c[2]), "+f"(c[3])
        : "r"(a[0]), "r"(a[1]), "r"(a[2]), "r"(a[3]), "r"(b[0]), "r"(b[1]));
}
__device__ __forceinline__ unsigned pack_h2(float lo, float hi) {
    __half2 h = __float22half2_rn(make_float2(lo, hi));
    return *(unsigned*)&h;
}

#define CP_ASYNC16(dst, src) \
    asm volatile("cp.async.cg.shared.global [%0], [%1], 16;" :: "r"(dst), "l"(src))
#define CP_COMMIT() asm volatile("cp.async.commit_group;" ::: "memory")
#define CP_WAIT1()  asm volatile("cp.async.wait_group 1;" ::: "memory")
#define CP_WAIT0()  asm volatile("cp.async.wait_group 0;" ::: "memory")

// ================= Kernel 0: gather + fp16 pre-convert (coalesced) =================
__global__ void __launch_bounds__(256) pre_cvt_h(
    const float* __restrict__ x,
    const float* __restrict__ Wq, const float* __restrict__ Wk, const float* __restrict__ Wv)
{
    const int blk  = blockIdx.x;
    const int rloc = threadIdx.x >> 5;
    const int lane = threadIdx.x & 31;

    const float* src;
    __half* dst;
    if (blk < 12544) {
        int p  = blk * 8 + rloc;
        int b  = p / 3136;
        int r  = p - b * 3136;
        int w  = r / 49;
        int t  = r - w * 49;
        int wy = w >> 3, wx = w & 7;
        int ty = t / 7,  tx = t - ty * 7;
        src = x + (size_t)((b * 56 + wy * 7 + ty) * 56 + wx * 7 + tx) * CDIM + lane * 8;
        dst = g_xh + (size_t)p * CDIM + lane * 8;
    } else {
        int r  = (blk - 12544) * 8 + rloc;
        int pr = r >> 8, wr = r & 255;
        const float* W = (pr == 0) ? Wq : ((pr == 1) ? Wk : Wv);
        src = W + (size_t)wr * CDIM + lane * 8;
        dst = g_wh + (size_t)r * CDIM + lane * 8;
    }
    float4 v0 = *(const float4*)(src);
    float4 v1 = *(const float4*)(src + 4);
    __half2 o[4];
    o[0] = __float22half2_rn(make_float2(v0.x, v0.y));
    o[1] = __float22half2_rn(make_float2(v0.z, v0.w));
    o[2] = __float22half2_rn(make_float2(v1.x, v1.y));
    o[3] = __float22half2_rn(make_float2(v1.z, v1.w));
    *(uint4*)dst = *(uint4*)o;
}

// ================= Kernel 1: QKV projection (fp16 HMMA, round-9 version) =================
#define HST 40
#define STAGE_HALVES (2 * 128 * HST)
#define PROJ_SMEM_BYTES (3 * STAGE_HALVES * 2)   // 61440

__global__ void __launch_bounds__(128) qkv_proj_fp16(
    const float* __restrict__ bq, const float* __restrict__ bk, const float* __restrict__ bv)
{
    extern __shared__ __align__(16) __half hsm[];

    const int tid  = threadIdx.x;
    const int warp = tid >> 5;
    const int lane = tid & 31;
    const int g    = lane >> 2;
    const int tig  = lane & 3;
    const int wm   = warp >> 1;
    const int wn   = warp & 1;

    const int p_block = blockIdx.y * 128;
    const int nb      = blockIdx.x;
    const int proj    = nb >> 1;
    const int dloc    = (nb & 1) * 128;
    const float* __restrict__ bias = (proj == 0) ? bq : ((proj == 1) ? bk : bv);

    const int lrow = tid >> 2;
    const int seg  = tid & 3;
    const __half* Ag = g_xh + (size_t)(p_block + lrow) * CDIM + seg * 8;
    const __half* Bg = g_wh + (size_t)(nb * 128 + lrow) * CDIM + seg * 8;
    const uint32_t sbase = smem_u32(hsm);

    auto issue_stage = [&](int stage, int chunk) {
        const uint32_t sA = sbase + (uint32_t)(stage * STAGE_HALVES) * 2;
        const uint32_t sB = sA + 128 * HST * 2;
        const int ko = chunk * 32;
        #pragma unroll
        for (int i = 0; i < 4; i++) {
            const uint32_t ro = (uint32_t)((lrow + 32 * i) * HST + seg * 8) * 2;
            CP_ASYNC16(sA + ro, Ag + (size_t)(32 * i) * CDIM + ko);
            CP_ASYNC16(sB + ro, Bg + (size_t)(32 * i) * CDIM + ko);
        }
        CP_COMMIT();
    };

    issue_stage(0, 0);
    issue_stage(1, 1);

    float acc[4][8][4] = {};

    int stage = 0;
    for (int kt = 0; kt < 8; kt++) {
        if (kt < 7) { CP_WAIT1(); } else { CP_WAIT0(); }
        __syncthreads();

        if (kt + 2 < 8) {
            int ns = stage + 2; if (ns >= 3) ns -= 3;
            issue_stage(ns, kt + 2);
        }

        const uint32_t* As32 = (const uint32_t*)(hsm + stage * STAGE_HALVES);
        const uint32_t* Bs32 = As32 + 128 * (HST / 2);

        #pragma unroll
        for (int ks = 0; ks < 2; ks++) {
            const int ko = ks * 8;
            unsigned a[4][4];
            unsigned b[8][2];
            #pragma unroll
            for (int mt = 0; mt < 4; mt++) {
                int row = wm * 64 + mt * 16 + g;
                a[mt][0] = As32[row * 20 + ko + tig];
                a[mt][1] = As32[(row + 8) * 20 + ko + tig];
                a[mt][2] = As32[row * 20 + ko + 4 + tig];
                a[mt][3] = As32[(row + 8) * 20 + ko + 4 + tig];
            }
            #pragma unroll
            for (int nt = 0; nt < 8; nt++) {
                int nrow = wn * 64 + nt * 8 + g;
                b[nt][0] = Bs32[nrow * 20 + ko + tig];
                b[nt][1] = Bs32[nrow * 20 + ko + 4 + tig];
            }
            #pragma unroll
            for (int mt = 0; mt < 4; mt++)
                #pragma unroll
                for (int nt = 0; nt < 8; nt++)
                    mma_f16(acc[mt][nt], a[mt], b[nt]);
        }

        stage++; if (stage == 3) stage = 0;
    }

    // ---- epilogue: bias add + fp16 store ----
    const size_t proj_off = (size_t)proj * M_TOK * CDIM;
    float bvs[8][2];
    #pragma unroll
    for (int nt = 0; nt < 8; nt++) {
        int d = dloc + wn * 64 + nt * 8 + tig * 2;
        bvs[nt][0] = bias[d];
        bvs[nt][1] = bias[d + 1];
    }
    #pragma unroll
    for (int mt = 0; mt < 4; mt++) {
        int p0 = p_block + wm * 64 + mt * 16 + g;
        __half* r0 = g_qkvh + proj_off + (size_t)p0 * CDIM;
        __half* r1 = r0 + 8 * CDIM;
        #pragma unroll
        for (int nt = 0; nt < 8; nt++) {
            int d = dloc + wn * 64 + nt * 8 + tig * 2;
            *(unsigned*)(r0 + d) = pack_h2(acc[mt][nt][0] + bvs[nt][0], acc[mt][nt][1] + bvs[nt][1]);
            *(unsigned*)(r1 + d) = pack_h2(acc[mt][nt][2] + bvs[nt][0], acc[mt][nt][3] + bvs[nt][1]);
        }
    }
}

// ================= Kernel 2: fp16 tensor-core attention (round-9 math,
//                   cp.async q/k prefetch + 8-CTA occupancy target) =================
#define QH_ST 40
#define VT_ST 72

__global__ void __launch_bounds__(128, 8) attn_kernel(float* __restrict__ out)
{
    __shared__ __align__(16) __half qs[64 * QH_ST];
    __shared__ __align__(16) __half ks[56 * QH_ST];
    __shared__ __align__(16) __half vt[32 * VT_ST];

    const int w   = blockIdx.x;
    const int h   = blockIdx.y;
    const int tid = threadIdx.x;

    const size_t base = (size_t)w * TWIN * CDIM + (size_t)h * HD;
    const uint32_t qs_b = smem_u32(qs);
    const uint32_t ks_b = smem_u32(ks);

    // ---- cp.async q,k (verbatim uint4 copies) issued FIRST ----
    for (int idx = tid; idx < 2 * TWIN * 4; idx += 128) {
        int mat = (idx >= TWIN * 4) ? 1 : 0;
        int rem = idx - mat * (TWIN * 4);
        int t   = rem >> 2;
        int seg = rem & 3;
        uint32_t dst = (mat ? ks_b : qs_b) + (uint32_t)(t * QH_ST + seg * 8) * 2;
        CP_ASYNC16(dst, g_qkvh + (size_t)mat * M_TOK * CDIM + base + (size_t)t * CDIM + seg * 8);
    }
    CP_COMMIT();

    // ---- zero pads (overlap with cp.async) ----
    for (int i = tid; i < 15 * QH_ST; i += 128) qs[49 * QH_ST + i] = __half(0.f);
    for (int i = tid; i < 7 * QH_ST; i += 128)  ks[49 * QH_ST + i] = __half(0.f);
    for (int i = tid; i < 32 * 16; i += 128) {
        int d = i >> 4, c = 49 + (i & 15);
        vt[d * VT_ST + c] = __half(0.f);
    }

    // ---- v transposed (LDG+STS, overlaps cp.async in flight) ----
    for (int idx = tid; idx < TWIN * 4; idx += 128) {
        int t   = idx >> 2;
        int seg = idx & 3;
        uint4 raw = *(const uint4*)(g_qkvh + (size_t)2 * M_TOK * CDIM + base + (size_t)t * CDIM + seg * 8);
        __half hv[8];
        *(uint4*)hv = raw;
        #pragma unroll
        for (int i = 0; i < 8; i++)
            vt[(seg * 8 + i) * VT_ST + t] = hv[i];
    }
    CP_WAIT0();
    __syncthreads();

    const int warp = tid >> 5;
    const int lane = tid & 31;
    const int g    = lane >> 2;
    const int tig  = lane & 3;
    const int i0   = warp * 16;

    const uint32_t* qw = (const uint32_t*)qs;
    const uint32_t* kw = (const uint32_t*)ks;
    const uint32_t* vw = (const uint32_t*)vt;

    float acc[7][4] = {};
    #pragma unroll
    for (int ks16 = 0; ks16 < 2; ks16++) {
        const int c0 = ks16 * 8;
        unsigned a[4];
        a[0] = qw[(i0 + g) * 20 + c0 + tig];
        a[1] = qw[(i0 + g + 8) * 20 + c0 + tig];
        a[2] = qw[(i0 + g) * 20 + c0 + 4 + tig];
        a[3] = qw[(i0 + g + 8) * 20 + c0 + 4 + tig];
        #pragma unroll
        for (int nt = 0; nt < 7; nt++) {
            unsigned b[2];
            b[0] = kw[(nt * 8 + g) * 20 + c0 + tig];
            b[1] = kw[(nt * 8 + g) * 20 + c0 + 4 + tig];
            mma_f16(acc[nt], a, b);
        }
    }

    #pragma unroll
    for (int nt = 0; nt < 7; nt++) {
        acc[nt][0] *= 0.0625f; acc[nt][1] *= 0.0625f;
        acc[nt][2] *= 0.0625f; acc[nt][3] *= 0.0625f;
    }
    acc[6][1] = -1e30f; acc[6][3] = -1e30f;
    if (tig > 0) { acc[6][0] = -1e30f; acc[6][2] = -1e30f; }

    float m0 = -1e30f, m1 = -1e30f;
    #pragma unroll
    for (int nt = 0; nt < 7; nt++) {
        m0 = fmaxf(m0, fmaxf(acc[nt][0], acc[nt][1]));
        m1 = fmaxf(m1, fmaxf(acc[nt][2], acc[nt][3]));
    }
    m0 = fmaxf(m0, __shfl_xor_sync(0xffffffffu, m0, 1));
    m0 = fmaxf(m0, __shfl_xor_sync(0xffffffffu, m0, 2));
    m1 = fmaxf(m1, __shfl_xor_sync(0xffffffffu, m1, 1));
    m1 = fmaxf(m1, __shfl_xor_sync(0xffffffffu, m1, 2));

    float s0 = 0.f, s1 = 0.f;
    #pragma unroll
    for (int nt = 0; nt < 7; nt++) {
        acc[nt][0] = __expf(acc[nt][0] - m0);
        acc[nt][1] = __expf(acc[nt][1] - m0);
        acc[nt][2] = __expf(acc[nt][2] - m1);
        acc[nt][3] = __expf(acc[nt][3] - m1);
        s0 += acc[nt][0] + acc[nt][1];
        s1 += acc[nt][2] + acc[nt][3];
    }
    s0 += __shfl_xor_sync(0xffffffffu, s0, 1);
    s0 += __shfl_xor_sync(0xffffffffu, s0, 2);
    s1 += __shfl_xor_sync(0xffffffffu, s1, 1);
    s1 += __shfl_xor_sync(0xffffffffu, s1, 2);
    const float inv0 = 1.f / s0, inv1 = 1.f / s1;
    #pragma unroll
    for (int nt = 0; nt < 7; nt++) {
        acc[nt][0] *= inv0; acc[nt][1] *= inv0;
        acc[nt][2] *= inv1; acc[nt][3] *= inv1;
    }

    float oacc[4][4] = {};
    #pragma unroll
    for (int t = 0; t < 4; t++) {
        const int n0 = 2 * t, n1 = 2 * t + 1;
        unsigned pa[4];
        pa[0] = pack_h2(acc[n0][0], acc[n0][1]);
        pa[1] = pack_h2(acc[n0][2], acc[n0][3]);
        pa[2] = (n1 < 7) ? pack_h2(acc[n1][0], acc[n1][1]) : 0u;
        pa[3] = (n1 < 7) ? pack_h2(acc[n1][2], acc[n1][3]) : 0u;
        #pragma unroll
        for (int dt = 0; dt < 4; dt++) {
            unsigned b[2];
            b[0] = vw[(dt * 8 + g) * 36 + 8 * t + tig];
            b[1] = vw[(dt * 8 + g) * 36 + 8 * t + tig + 4];
            mma_f16(oacc[dt], pa, b);
        }
    }

    const int row0 = i0 + g;
    const int row1 = i0 + 8 + g;
    if (row0 < TWIN) {
        float* o = out + ((size_t)w * TWIN + row0) * CDIM + (size_t)h * HD;
        #pragma unroll
        for (int dt = 0; dt < 4; dt++)
            *(float2*)&o[dt * 8 + tig * 2] = make_float2(oacc[dt][0], oacc[dt][1]);
    }
    if (row1 < TWIN) {
        float* o = out + ((size_t)w * TWIN + row1) * CDIM + (size_t)h * HD;
        #pragma unroll
        for (int dt = 0; dt < 4; dt++)
            *(float2*)&o[dt * 8 + tig * 2] = make_float2(oacc[dt][2], oacc[dt][3]);
    }
}

// ================= launch =================
extern "C" void kernel_launch(void* const* d_in, const int* in_sizes, int n_in,
                              void* d_out, int out_size) {
    const float* x  = (const float*)d_in[0];
    const float* Wq = (const float*)d_in[1];
    const float* bq = (const float*)d_in[2];
    const float* Wk = (const float*)d_in[3];
    const float* bk = (const float*)d_in[4];
    const float* Wv = (const float*)d_in[5];
    const float* bv = (const float*)d_in[6];
    float* out = (float*)d_out;

    cudaFuncSetAttribute(qkv_proj_fp16,
                         cudaFuncAttributeMaxDynamicSharedMemorySize, PROJ_SMEM_BYTES);

    pre_cvt_h<<<12640, 256>>>(x, Wq, Wk, Wv);

    dim3 g1(6, M_TOK / 128);
    qkv_proj_fp16<<<g1, 128, PROJ_SMEM_BYTES>>>(bq, bk, bv);

    dim3 g2(NWIN, NHEADS);
    attn_kernel<<<g2, 128>>>(out);
}